// round 2
// baseline (speedup 1.0000x reference)
#include <cuda_runtime.h>

// SO3 projection, reduced from the SVD reference:
//   Rb    = sign(det A) * U_p^T           (U_p = polar factor of A)
//   trans = -sqrt(3) * U_p^T t / ||A||_F  (sign cancels)
// U_p via determinantally-scaled Newton polar iteration, then unscaled
// Newton once in the convergence basin (zeta ~= 1 there, so the
// LG2/EX2 pair is pure critical-path overhead).
//
// 2 matrices per thread, interleaved, to double the independent
// dependency chains per warp (the R1 profile showed a latency-bound
// kernel: all pipes < 50%, issue 64%).

#define SCALED_ITERS   4
#define UNSCALED_ITERS 2

__global__ void __launch_bounds__(256)
so3_project_kernel(const float4* __restrict__ in, float4* __restrict__ out, int n2)
{
    int tid = blockIdx.x * blockDim.x + threadIdx.x;
    if (tid >= n2) return;
    int b0 = 2 * tid;

    float x[2][9];     // working matrix (row-major)
    float tv[2][3];    // translation
    float sg[2];       // sign(det A)
    float ts[2];       // -sqrt(3)/||A||_F

#pragma unroll
    for (int m = 0; m < 2; ++m) {
        const float4* p = in + 4 * (b0 + m);
        float4 r0 = p[0];
        float4 r1 = p[1];
        float4 r2 = p[2];
        x[m][0] = r0.x; x[m][1] = r0.y; x[m][2] = r0.z; tv[m][0] = r0.w;
        x[m][3] = r1.x; x[m][4] = r1.y; x[m][5] = r1.z; tv[m][1] = r1.w;
        x[m][6] = r2.x; x[m][7] = r2.y; x[m][8] = r2.z; tv[m][2] = r2.w;

        float detA = x[m][0] * (x[m][4] * x[m][8] - x[m][5] * x[m][7])
                   - x[m][1] * (x[m][3] * x[m][8] - x[m][5] * x[m][6])
                   + x[m][2] * (x[m][3] * x[m][7] - x[m][4] * x[m][6]);
        float fro2 = x[m][0] * x[m][0] + x[m][1] * x[m][1] + x[m][2] * x[m][2]
                   + x[m][3] * x[m][3] + x[m][4] * x[m][4] + x[m][5] * x[m][5]
                   + x[m][6] * x[m][6] + x[m][7] * x[m][7] + x[m][8] * x[m][8];
        sg[m] = (detA < 0.0f) ? -1.0f : 1.0f;
        ts[m] = -1.7320508075688772f * rsqrtf(fro2);
    }

    // Scaled Newton: X <- 0.5*(zeta*X + (1/zeta)*X^{-T}), zeta = |det|^{-1/3}
#pragma unroll
    for (int it = 0; it < SCALED_ITERS; ++it) {
#pragma unroll
        for (int m = 0; m < 2; ++m) {
            float c0 = x[m][4] * x[m][8] - x[m][5] * x[m][7];
            float c1 = x[m][5] * x[m][6] - x[m][3] * x[m][8];
            float c2 = x[m][3] * x[m][7] - x[m][4] * x[m][6];
            float c3 = x[m][2] * x[m][7] - x[m][1] * x[m][8];
            float c4 = x[m][0] * x[m][8] - x[m][2] * x[m][6];
            float c5 = x[m][1] * x[m][6] - x[m][0] * x[m][7];
            float c6 = x[m][1] * x[m][5] - x[m][2] * x[m][4];
            float c7 = x[m][2] * x[m][3] - x[m][0] * x[m][5];
            float c8 = x[m][0] * x[m][4] - x[m][1] * x[m][3];
            float d  = x[m][0] * c0 + x[m][1] * c1 + x[m][2] * c2;

            float ad   = fmaxf(fabsf(d), 1e-30f);
            float zeta = __powf(ad, -0.3333333333f);
            float hz   = 0.5f * zeta;
            float izd  = __fdividef(0.5f, zeta * d);

            x[m][0] = hz * x[m][0] + izd * c0;
            x[m][1] = hz * x[m][1] + izd * c1;
            x[m][2] = hz * x[m][2] + izd * c2;
            x[m][3] = hz * x[m][3] + izd * c3;
            x[m][4] = hz * x[m][4] + izd * c4;
            x[m][5] = hz * x[m][5] + izd * c5;
            x[m][6] = hz * x[m][6] + izd * c6;
            x[m][7] = hz * x[m][7] + izd * c7;
            x[m][8] = hz * x[m][8] + izd * c8;
        }
    }

    // Unscaled Newton: X <- 0.5*(X + C/d)  (zeta ~= 1 near convergence)
#pragma unroll
    for (int it = 0; it < UNSCALED_ITERS; ++it) {
#pragma unroll
        for (int m = 0; m < 2; ++m) {
            float c0 = x[m][4] * x[m][8] - x[m][5] * x[m][7];
            float c1 = x[m][5] * x[m][6] - x[m][3] * x[m][8];
            float c2 = x[m][3] * x[m][7] - x[m][4] * x[m][6];
            float c3 = x[m][2] * x[m][7] - x[m][1] * x[m][8];
            float c4 = x[m][0] * x[m][8] - x[m][2] * x[m][6];
            float c5 = x[m][1] * x[m][6] - x[m][0] * x[m][7];
            float c6 = x[m][1] * x[m][5] - x[m][2] * x[m][4];
            float c7 = x[m][2] * x[m][3] - x[m][0] * x[m][5];
            float c8 = x[m][0] * x[m][4] - x[m][1] * x[m][3];
            float d  = x[m][0] * c0 + x[m][1] * c1 + x[m][2] * c2;

            float izd = __fdividef(0.5f, d);

            x[m][0] = 0.5f * x[m][0] + izd * c0;
            x[m][1] = 0.5f * x[m][1] + izd * c1;
            x[m][2] = 0.5f * x[m][2] + izd * c2;
            x[m][3] = 0.5f * x[m][3] + izd * c3;
            x[m][4] = 0.5f * x[m][4] + izd * c4;
            x[m][5] = 0.5f * x[m][5] + izd * c5;
            x[m][6] = 0.5f * x[m][6] + izd * c6;
            x[m][7] = 0.5f * x[m][7] + izd * c7;
            x[m][8] = 0.5f * x[m][8] + izd * c8;
        }
    }

    // Emit: Rb = s * X^T, trans_i = ts * (col_i(X) . t), row3 = e3
#pragma unroll
    for (int m = 0; m < 2; ++m) {
        float tr0 = ts[m] * (x[m][0] * tv[m][0] + x[m][3] * tv[m][1] + x[m][6] * tv[m][2]);
        float tr1 = ts[m] * (x[m][1] * tv[m][0] + x[m][4] * tv[m][1] + x[m][7] * tv[m][2]);
        float tr2 = ts[m] * (x[m][2] * tv[m][0] + x[m][5] * tv[m][1] + x[m][8] * tv[m][2]);

        float4* q = out + 4 * (b0 + m);
        float s = sg[m];
        q[0] = make_float4(s * x[m][0], s * x[m][3], s * x[m][6], tr0);
        q[1] = make_float4(s * x[m][1], s * x[m][4], s * x[m][7], tr1);
        q[2] = make_float4(s * x[m][2], s * x[m][5], s * x[m][8], tr2);
        q[3] = make_float4(0.0f, 0.0f, 0.0f, 1.0f);
    }
}

extern "C" void kernel_launch(void* const* d_in, const int* in_sizes, int n_in,
                              void* d_out, int out_size)
{
    const int n  = in_sizes[0] / 16;     // number of 4x4 matrices
    const int n2 = n / 2;                // 2 matrices per thread (n is even)
    const int threads = 256;
    const int blocks  = (n2 + threads - 1) / threads;
    so3_project_kernel<<<blocks, threads>>>(
        (const float4*)d_in[0], (float4*)d_out, n2);
}

// round 3
// speedup vs baseline: 1.2220x; 1.2220x over previous
#include <cuda_runtime.h>

// SO3 projection, reduced from the SVD reference:
//   Rb    = sign(det A) * U_p^T           (U_p = polar factor of A)
//   trans = -sqrt(3) * U_p^T t / ||A||_F  (sign cancels)
//
// U_p via determinantally-scaled Newton polar iteration (4 iters), then
// unscaled Newton (2 iters) in the convergence basin where zeta ~= 1 and
// the LG2/EX2 scaling is pure critical-path overhead. R2 validated this
// schedule at rel_err ~= 2e-7 (tolerance is 1e-3).
//
// 1 matrix per thread: R2 showed that 2 matrices/thread gets spilled to
// local memory at the 32-reg budget and regresses badly.

__global__ void __launch_bounds__(256, 4)
so3_project_kernel(const float4* __restrict__ in, float4* __restrict__ out, int n)
{
    int b = blockIdx.x * blockDim.x + threadIdx.x;
    if (b >= n) return;

    float4 r0 = in[4 * b + 0];
    float4 r1 = in[4 * b + 1];
    float4 r2 = in[4 * b + 2];

    float x00 = r0.x, x01 = r0.y, x02 = r0.z, t0 = r0.w;
    float x10 = r1.x, x11 = r1.y, x12 = r1.z, t1 = r1.w;
    float x20 = r2.x, x21 = r2.y, x22 = r2.z, t2 = r2.w;

    float detA = x00 * (x11 * x22 - x12 * x21)
               - x01 * (x10 * x22 - x12 * x20)
               + x02 * (x10 * x21 - x11 * x20);
    float fro2 = x00 * x00 + x01 * x01 + x02 * x02
               + x10 * x10 + x11 * x11 + x12 * x12
               + x20 * x20 + x21 * x21 + x22 * x22;
    float s  = (detA < 0.0f) ? -1.0f : 1.0f;
    float ts = -1.7320508075688772f * rsqrtf(fro2);

    // ---- 4 scaled Newton iterations: X <- 0.5*(zeta*X + (1/zeta)*X^{-T})
#pragma unroll
    for (int it = 0; it < 4; ++it) {
        float c00 = x11 * x22 - x12 * x21;
        float c01 = x12 * x20 - x10 * x22;
        float c02 = x10 * x21 - x11 * x20;
        float c10 = x02 * x21 - x01 * x22;
        float c11 = x00 * x22 - x02 * x20;
        float c12 = x01 * x20 - x00 * x21;
        float c20 = x01 * x12 - x02 * x11;
        float c21 = x02 * x10 - x00 * x12;
        float c22 = x00 * x11 - x01 * x10;
        float d   = x00 * c00 + x01 * c01 + x02 * c02;

        float ad   = fmaxf(fabsf(d), 1e-30f);
        float zeta = __powf(ad, -0.3333333333f);   // |det(zeta*X)| ~= 1
        float hz   = 0.5f * zeta;
        float izd  = __fdividef(0.5f, zeta * d);

        x00 = hz * x00 + izd * c00;
        x01 = hz * x01 + izd * c01;
        x02 = hz * x02 + izd * c02;
        x10 = hz * x10 + izd * c10;
        x11 = hz * x11 + izd * c11;
        x12 = hz * x12 + izd * c12;
        x20 = hz * x20 + izd * c20;
        x21 = hz * x21 + izd * c21;
        x22 = hz * x22 + izd * c22;
    }

    // ---- 2 unscaled Newton iterations: X <- 0.5*(X + C/d)
#pragma unroll
    for (int it = 0; it < 2; ++it) {
        float c00 = x11 * x22 - x12 * x21;
        float c01 = x12 * x20 - x10 * x22;
        float c02 = x10 * x21 - x11 * x20;
        float c10 = x02 * x21 - x01 * x22;
        float c11 = x00 * x22 - x02 * x20;
        float c12 = x01 * x20 - x00 * x21;
        float c20 = x01 * x12 - x02 * x11;
        float c21 = x02 * x10 - x00 * x12;
        float c22 = x00 * x11 - x01 * x10;
        float d   = x00 * c00 + x01 * c01 + x02 * c02;

        float izd = __fdividef(0.5f, d);

        x00 = 0.5f * x00 + izd * c00;
        x01 = 0.5f * x01 + izd * c01;
        x02 = 0.5f * x02 + izd * c02;
        x10 = 0.5f * x10 + izd * c10;
        x11 = 0.5f * x11 + izd * c11;
        x12 = 0.5f * x12 + izd * c12;
        x20 = 0.5f * x20 + izd * c20;
        x21 = 0.5f * x21 + izd * c21;
        x22 = 0.5f * x22 + izd * c22;
    }

    // Emit: Rb = s * X^T, trans_i = ts * (col_i(X) . t), row3 = e3
    float tr0 = ts * (x00 * t0 + x10 * t1 + x20 * t2);
    float tr1 = ts * (x01 * t0 + x11 * t1 + x21 * t2);
    float tr2 = ts * (x02 * t0 + x12 * t1 + x22 * t2);

    out[4 * b + 0] = make_float4(s * x00, s * x10, s * x20, tr0);
    out[4 * b + 1] = make_float4(s * x01, s * x11, s * x21, tr1);
    out[4 * b + 2] = make_float4(s * x02, s * x12, s * x22, tr2);
    out[4 * b + 3] = make_float4(0.0f, 0.0f, 0.0f, 1.0f);
}

extern "C" void kernel_launch(void* const* d_in, const int* in_sizes, int n_in,
                              void* d_out, int out_size)
{
    const int n = in_sizes[0] / 16;
    const int threads = 256;
    const int blocks  = (n + threads - 1) / threads;
    so3_project_kernel<<<blocks, threads>>>(
        (const float4*)d_in[0], (float4*)d_out, n);
}

// round 5
// speedup vs baseline: 1.4147x; 1.1577x over previous
#include <cuda_runtime.h>
#include <math.h>

// SO3 projection, reduced from the SVD reference:
//   Rb    = sign(det A) * U_p^T           (U_p = polar factor of A)
//   trans = -sqrt(3) * U_p^T t / ||A||_F  (sign cancels)
//
// U_p via determinantally-scaled Newton polar iteration (4 iters), then
// unscaled Newton (2 iters). Schedule validated at rel_err ~= 2e-7.
//
// Latency/occupancy-bound kernel (R1-R3 evidence). Force the 32-reg
// budget (R1 proves the math fits spill-free) and split the per-
// iteration MUFU chain (LG2->EX2->RCP serial) into parallel chains:
//   l = log2|d|;  hz = 0.5*2^(-l/3);  hzi = 0.5*2^(+l/3);  rd = rcp(d)
// so RCP(d) overlaps the LG2/EX2 pair instead of waiting on zeta*d.

__global__ void __launch_bounds__(256, 8)   // caps regs at 32
so3_project_kernel(const float4* __restrict__ in, float4* __restrict__ out, int n)
{
    int b = blockIdx.x * blockDim.x + threadIdx.x;
    if (b >= n) return;

    float4 r0 = in[4 * b + 0];
    float4 r1 = in[4 * b + 1];
    float4 r2 = in[4 * b + 2];

    float x00 = r0.x, x01 = r0.y, x02 = r0.z, t0 = r0.w;
    float x10 = r1.x, x11 = r1.y, x12 = r1.z, t1 = r1.w;
    float x20 = r2.x, x21 = r2.y, x22 = r2.z, t2 = r2.w;

    float detA = x00 * (x11 * x22 - x12 * x21)
               - x01 * (x10 * x22 - x12 * x20)
               + x02 * (x10 * x21 - x11 * x20);
    float fro2 = x00 * x00 + x01 * x01 + x02 * x02
               + x10 * x10 + x11 * x11 + x12 * x12
               + x20 * x20 + x21 * x21 + x22 * x22;
    float s  = (detA < 0.0f) ? -1.0f : 1.0f;
    float ts = -1.7320508075688772f * rsqrtf(fro2);

    // ---- 4 scaled Newton iterations:
    //   X <- 0.5*zeta*X + 0.5*(1/zeta)*C/d,  zeta = |d|^{-1/3}
#pragma unroll
    for (int it = 0; it < 4; ++it) {
        float c00 = x11 * x22 - x12 * x21;
        float c01 = x12 * x20 - x10 * x22;
        float c02 = x10 * x21 - x11 * x20;
        float c10 = x02 * x21 - x01 * x22;
        float c11 = x00 * x22 - x02 * x20;
        float c12 = x01 * x20 - x00 * x21;
        float c20 = x01 * x12 - x02 * x11;
        float c21 = x02 * x10 - x00 * x12;
        float c22 = x00 * x11 - x01 * x10;
        float d   = x00 * c00 + x01 * c01 + x02 * c02;

        float ad  = fmaxf(fabsf(d), 1e-30f);
        float rd  = __fdividef(1.0f, d);             // RCP: parallel chain
        float l   = __log2f(ad);                     // LG2
        float hz  = 0.5f * exp2f(-0.3333333333f * l);   // 0.5*|d|^{-1/3}
        float hzi = 0.5f * exp2f( 0.3333333333f * l);   // 0.5*|d|^{+1/3}
        float izd = hzi * rd;                        // 0.5*|d|^{1/3}/d

        x00 = hz * x00 + izd * c00;
        x01 = hz * x01 + izd * c01;
        x02 = hz * x02 + izd * c02;
        x10 = hz * x10 + izd * c10;
        x11 = hz * x11 + izd * c11;
        x12 = hz * x12 + izd * c12;
        x20 = hz * x20 + izd * c20;
        x21 = hz * x21 + izd * c21;
        x22 = hz * x22 + izd * c22;
    }

    // ---- 2 unscaled Newton iterations: X <- 0.5*(X + C/d)
#pragma unroll
    for (int it = 0; it < 2; ++it) {
        float c00 = x11 * x22 - x12 * x21;
        float c01 = x12 * x20 - x10 * x22;
        float c02 = x10 * x21 - x11 * x20;
        float c10 = x02 * x21 - x01 * x22;
        float c11 = x00 * x22 - x02 * x20;
        float c12 = x01 * x20 - x00 * x21;
        float c20 = x01 * x12 - x02 * x11;
        float c21 = x02 * x10 - x00 * x12;
        float c22 = x00 * x11 - x01 * x10;
        float d   = x00 * c00 + x01 * c01 + x02 * c02;

        float izd = __fdividef(0.5f, d);

        x00 = 0.5f * x00 + izd * c00;
        x01 = 0.5f * x01 + izd * c01;
        x02 = 0.5f * x02 + izd * c02;
        x10 = 0.5f * x10 + izd * c10;
        x11 = 0.5f * x11 + izd * c11;
        x12 = 0.5f * x12 + izd * c12;
        x20 = 0.5f * x20 + izd * c20;
        x21 = 0.5f * x21 + izd * c21;
        x22 = 0.5f * x22 + izd * c22;
    }

    // Emit: Rb = s * X^T, trans_i = ts * (col_i(X) . t), row3 = e3
    float tr0 = ts * (x00 * t0 + x10 * t1 + x20 * t2);
    float tr1 = ts * (x01 * t0 + x11 * t1 + x21 * t2);
    float tr2 = ts * (x02 * t0 + x12 * t1 + x22 * t2);

    out[4 * b + 0] = make_float4(s * x00, s * x10, s * x20, tr0);
    out[4 * b + 1] = make_float4(s * x01, s * x11, s * x21, tr1);
    out[4 * b + 2] = make_float4(s * x02, s * x12, s * x22, tr2);
    out[4 * b + 3] = make_float4(0.0f, 0.0f, 0.0f, 1.0f);
}

extern "C" void kernel_launch(void* const* d_in, const int* in_sizes, int n_in,
                              void* d_out, int out_size)
{
    const int n = in_sizes[0] / 16;
    const int threads = 256;
    const int blocks  = (n + threads - 1) / threads;
    so3_project_kernel<<<blocks, threads>>>(
        (const float4*)d_in[0], (float4*)d_out, n);
}